// round 17
// baseline (speedup 1.0000x reference)
#include <cuda_runtime.h>
#include <math.h>

// Problem shape (fixed by the benchmark):
// video [B=8, C=1024, T=64, W=14, H=14] fp32
// params mu_x, mu_y, sigma_x, sigma_y: [N=3] fp32
// out [B, C*N] = einsum('bctwh,nwh->bcn', video, filters) / T
//
// Single-kernel design: block 0 computes the 3 normalized Gaussian filters
// (MUFU, ~1us) and publishes them via g_flag; other CTAs spin only if they
// start before block 0 finishes (wave 1 only), prefetching their slab head
// into L2 while waiting. The last CTA to finish resets the flag so every
// call of kernel_launch runs the identical protocol (graph-replay safe).
// This removes the ~2-3.6us two-kernel graph overhead measured consistently
// across rounds (single-kernel rounds showed total-kernel ~= 0).
#define N_FILT 3
#define W_DIM 14
#define H_DIM 14
#define WH 196              // W*H
#define WH4 49              // WH/4
#define T_DIM 64
#define T_GROUPS 5          // time-slices per CTA thread-group
#define ACTIVE_THREADS (WH4 * T_GROUPS)  // 245
#define SLAB (T_DIM * WH)   // 12544 floats per (b,c)
#define SLAB4 (SLAB / 4)    // 3136 float4 per (b,c)

// Filters pre-scaled by 1/(sum+eps) * (1/T).
__device__ float4 g_filt4[N_FILT * WH4];
__device__ int g_flag = 0;           // 0 = filters not ready
__device__ unsigned int g_done = 0;  // completion counter for flag reset

// Fast tanh via MUFU exp: 1 - 2/(e^{2x}+1). Rel err ~1e-6.
__device__ __forceinline__ float fast_tanh(float x) {
    float t = __expf(2.0f * x);
    return 1.0f - 2.0f / (t + 1.0f);
}
__device__ __forceinline__ float fast_sigmoid(float x) {
    return 1.0f / (1.0f + __expf(-x));
}

// ---------------------------------------------------------------------------
__global__ __launch_bounds__(256, 8)
void pool_kernel(const float4* __restrict__ video4,
                 const float* __restrict__ mu_x,
                 const float* __restrict__ mu_y,
                 const float* __restrict__ sigma_x,
                 const float* __restrict__ sigma_y,
                 float* __restrict__ out) {
    const int bc = blockIdx.x;
    const int tid = threadIdx.x;
    const int wid = tid >> 5;
    const int lid = tid & 31;

    __shared__ float part[8][N_FILT];   // reused: filter sums, then epilogue

    const int g = tid / WH4;            // time-group 0..4 (for tid<245)
    const int p = tid - g * WH4;        // spatial float4 position 0..48
    const float4* vp = video4 + bc * SLAB4 + g * WH4 + p;

    if (bc == 0) {
        // ---- Block 0: compute filters (MUFU), publish, proceed ----------
        #pragma unroll
        for (int n = 0; n < N_FILT; n++) {
            float mx = fast_tanh(mu_x[n]);
            float my = fast_tanh(mu_y[n]);
            float sx = __expf(1.5f - 2.0f * fast_sigmoid(sigma_x[n]));
            float sy = __expf(1.5f - 2.0f * fast_sigmoid(sigma_y[n]));
            float inv_x = 1.0f / (sx * sx + 1e-6f);
            float inv_y = 1.0f / (sy * sy + 1e-6f);
            float mux = (float)(W_DIM - 1) * ((mx + 1.0f) * 0.5f);
            float muy = (float)(H_DIM - 1) * ((my + 1.0f) * 0.5f);

            float v = 0.0f;
            if (tid < WH) {
                int w = tid / H_DIM;
                int h = tid - w * H_DIM;
                float dx = (float)w - mux;
                float dy = (float)h - muy;
                v = __expf(-0.5f * (dx * dx * inv_x + dy * dy * inv_y));
            }
            float s = v;
            #pragma unroll
            for (int off = 16; off > 0; off >>= 1)
                s += __shfl_xor_sync(0xFFFFFFFFu, s, off);
            if (lid == 0) part[wid][n] = s;
            __syncthreads();
            float tot = 0.0f;
            #pragma unroll
            for (int w8 = 0; w8 < 8; w8++) tot += part[w8][n];
            float scale = 1.0f / ((tot + 1e-6f) * (float)T_DIM);
            if (tid < WH) {
                ((float*)g_filt4)[n * WH + tid] = v * scale;
            }
            __syncthreads();
        }
        __threadfence();                 // filters visible device-wide
        if (tid == 0) atomicExch(&g_flag, 1);
        __syncthreads();
    } else {
        // ---- Other blocks: prefetch slab head to L2, spin if needed -----
        if (tid < ACTIVE_THREADS) {
            asm volatile("prefetch.global.L2 [%0];" :: "l"(vp));
            asm volatile("prefetch.global.L2 [%0];" :: "l"(vp + T_GROUPS * WH4));
        }
        if (tid == 0) {
            while (atomicAdd(&g_flag, 0) == 0) { __nanosleep(32); }
        }
        __syncthreads();                 // orders filter reads after the spin
    }

    // ---- Hot loop (proven config: 1 LDG.128 + 12 FFMA, plain unroll-2) --
    float a0 = 0.0f, a1 = 0.0f, a2 = 0.0f;

    if (tid < ACTIVE_THREADS) {
        // plain loads (coherent): g_filt4 written this launch
        const float4 f0 = *((const float4*)g_filt4 + p);
        const float4 f1 = *((const float4*)g_filt4 + WH4 + p);
        const float4 f2 = *((const float4*)g_filt4 + 2 * WH4 + p);

        const int iters = (g == T_GROUPS - 1) ? 12 : 13;  // ceil((64-g)/5)

        #pragma unroll 2
        for (int it = 0; it < iters; it++) {
            float4 v = __ldg(vp);
            vp += T_GROUPS * WH4;
            a0 += v.x * f0.x + v.y * f0.y + v.z * f0.z + v.w * f0.w;
            a1 += v.x * f1.x + v.y * f1.y + v.z * f1.z + v.w * f1.w;
            a2 += v.x * f2.x + v.y * f2.y + v.z * f2.z + v.w * f2.w;
        }
    }

    // warp reduction (all 256 threads participate; inactive ones carry zeros)
    #pragma unroll
    for (int off = 16; off > 0; off >>= 1) {
        a0 += __shfl_xor_sync(0xFFFFFFFFu, a0, off);
        a1 += __shfl_xor_sync(0xFFFFFFFFu, a1, off);
        a2 += __shfl_xor_sync(0xFFFFFFFFu, a2, off);
    }

    __syncthreads();   // part[] reused by block 0's filter phase
    if (lid == 0) {
        part[wid][0] = a0;
        part[wid][1] = a1;
        part[wid][2] = a2;
    }
    __syncthreads();

    if (tid < N_FILT) {
        float s = 0.0f;
        #pragma unroll
        for (int w8 = 0; w8 < 8; w8++) s += part[w8][tid];
        out[bc * N_FILT + tid] = s;
    }

    // ---- Reset protocol: last CTA clears the flag (graph-replay safe) ---
    if (tid == 0) {
        __threadfence();
        unsigned int old = atomicInc(&g_done, gridDim.x - 1); // wraps to 0
        if (old == gridDim.x - 1) {
            atomicExch(&g_flag, 0);
        }
    }
}

// ---------------------------------------------------------------------------
extern "C" void kernel_launch(void* const* d_in, const int* in_sizes, int n_in,
                              void* d_out, int out_size) {
    const float* video   = (const float*)d_in[0];
    const float* mu_x    = (const float*)d_in[1];
    const float* mu_y    = (const float*)d_in[2];
    const float* sigma_x = (const float*)d_in[3];
    const float* sigma_y = (const float*)d_in[4];
    float* out = (float*)d_out;

    const int n_bc = in_sizes[0] / SLAB;  // B*C = 8192

    pool_kernel<<<n_bc, 256>>>((const float4*)video,
                               mu_x, mu_y, sigma_x, sigma_y, out);
}